// round 14
// baseline (speedup 1.0000x reference)
#include <cuda_runtime.h>

#define NB 8
#define OP 400
#define MA 200
#define F 64
#define NBM (NB*MA)           // 1600
#define NSPLIT 2
#define OPH (OP/NSPLIT)       // 200 n's per split

// Scratch (allocation-free rule: __device__ globals)
__device__ float g_hop[NB*OP*F];   // h_op = x @ W_op
__device__ float g_sop[NB*OP];     // h_op . a_op
__device__ float g_h  [NB*MA*F];   // h = y @ W_ma
__device__ float g_sma[NB*MA];     // h . a_ma
__device__ float g_vedge[F];       // W_edge @ a_edge
// per-split partials (always fully written by main kernel -> no zeroing)
__device__ float g_paccz[NSPLIT*NBM*F];
__device__ float g_pacch[NSPLIT*NBM*F];
__device__ float g_pd   [NSPLIT*NBM];

__device__ __forceinline__ float warp_sum(float v) {
    v += __shfl_xor_sync(0xffffffffu, v, 16);
    v += __shfl_xor_sync(0xffffffffu, v, 8);
    v += __shfl_xor_sync(0xffffffffu, v, 4);
    v += __shfl_xor_sync(0xffffffffu, v, 2);
    v += __shfl_xor_sync(0xffffffffu, v, 1);
    return v;
}

// ---------------------------------------------------------------------------
// Prep kernel: small GEMVs.
// ---------------------------------------------------------------------------
__global__ void prep_kernel(const float* __restrict__ x, const float* __restrict__ y,
                            const float* __restrict__ Wop, const float* __restrict__ Wma,
                            const float* __restrict__ Wedge, const float* __restrict__ att)
{
    int blk = blockIdx.x;
    int t = threadIdx.x;

    if (blk == NB*OP + NB*MA) {
        float acc = 0.f;
        #pragma unroll
        for (int f = 0; f < F; f++) acc += Wedge[t*F + f] * att[2*F + f];
        g_vedge[t] = acc;
        return;
    }

    const float* in; const float* W; const float* a;
    float* hout; float* sout;
    if (blk < NB*OP) {
        int row = blk;
        in = x + row*F; W = Wop; a = att;
        hout = g_hop + row*F; sout = g_sop + row;
    } else {
        int row = blk - NB*OP;
        in = y + row*F; W = Wma; a = att + F;
        hout = g_h + row*F; sout = g_sma + row;
    }

    __shared__ float srow[F];
    __shared__ float sred[2];
    srow[t] = in[t];
    __syncthreads();

    float acc = 0.f;
    #pragma unroll
    for (int i = 0; i < F; i++) acc += srow[i] * W[i*F + t];
    hout[t] = acc;

    float v = warp_sum(acc * a[t]);
    if ((t & 31) == 0) sred[t >> 5] = v;
    __syncthreads();
    if (t == 0) sout[0] = sred[0] + sred[1];
}

// ---------------------------------------------------------------------------
// Main kernel: grid (NBM, NSPLIT), 64 threads, NO reg cap (R10's cap caused
// spills). CTA (bm, s) handles n in [s*200, (s+1)*200): compaction + single
// pass softmax partials. Half-warp-per-n float4; unroll 4 -> 8 z LDG.128 in
// flight per warp. 3200 CTAs -> ~21.6 resident/SM = ~43 warps/SM, one wave.
// ---------------------------------------------------------------------------
__global__ void __launch_bounds__(64) edge_gat_kernel(
    const float*  __restrict__ z,
    const int*    __restrict__ adj)
{
    const int bm = blockIdx.x;
    const int sp = blockIdx.y;
    const int b = bm / MA;
    const int m = bm % MA;
    const int tid = threadIdx.x;
    const int w = tid >> 5;        // 0 or 1
    const int lane = tid & 31;
    const int l4 = lane & 15;
    const int hh = lane >> 4;

    __shared__ int   s_cnt;
    __shared__ int   s_idx[OPH];
    __shared__ float s_sopc[OPH];
    __shared__ float4 s_pz4[2*16];
    __shared__ float4 s_ph4[2*16];
    __shared__ float s_pd[2];

    if (tid == 0) s_cnt = 0;
    __syncthreads();

    const int nbase = sp * OPH;
    // ballot-compaction; warp-uniform trip count: 256 = 4 iters for 64 thr
    for (int i = tid; i < 256; i += 64) {
        int mk = 0;
        float sop = 0.f;
        if (i < OPH) {
            int n = nbase + i;
            mk = adj[(b*OP + n)*MA + m];     // adjT[b,m,n]
            if (mk) sop = g_sop[b*OP + n];
        }
        unsigned ball = __ballot_sync(0xffffffffu, mk != 0);
        int base = 0;
        if (lane == 0 && ball) base = atomicAdd(&s_cnt, __popc(ball));
        base = __shfl_sync(0xffffffffu, base, 0);
        if (mk) {
            int off = base + __popc(ball & ((1u << lane) - 1u));
            s_idx[off]  = nbase + i;
            s_sopc[off] = sop;
        }
    }
    const float  sma = g_sma[bm];
    const float4 ve  = ((const float4*)g_vedge)[l4];
    __syncthreads();
    const int cnt = s_cnt;
    const int U = (cnt + 1) >> 1;    // units of 2 n's

    float4 accz = make_float4(0.f, 0.f, 0.f, 0.f);
    float4 acch = make_float4(0.f, 0.f, 0.f, 0.f);
    float  denom = 0.f;

    const float4* zb4 = (const float4*)z;
    const float4* hb4 = (const float4*)g_hop;

    // warp w: units u = w + 2k, unrolled x4 -> 8 n (8 z LDG.128) in flight
    #pragma unroll 1
    for (int u0 = w; u0 < U; u0 += 8) {
        bool  ok[4]; float sop[4];
        float4 zv[4], hv[4];
        #pragma unroll
        for (int t = 0; t < 4; t++) {
            int u  = u0 + 2*t;
            int jn = 2*u + hh;
            ok[t] = (u < U) && (jn < cnt);
            int jc = ok[t] ? jn : 0;
            int n  = s_idx[jc];
            sop[t] = s_sopc[jc];
            if (ok[t]) {
                zv[t] = zb4[((b*OP + n)*MA + m)*16 + l4];
                hv[t] = hb4[(b*OP + n)*16 + l4];
            } else {
                zv[t] = make_float4(0.f,0.f,0.f,0.f);
                hv[t] = make_float4(0.f,0.f,0.f,0.f);
            }
        }
        float d[4];
        #pragma unroll
        for (int t = 0; t < 4; t++)
            d[t] = zv[t].x*ve.x + zv[t].y*ve.y + zv[t].z*ve.z + zv[t].w*ve.w;
        #pragma unroll
        for (int o = 8; o; o >>= 1) {
            #pragma unroll
            for (int t = 0; t < 4; t++)
                d[t] += __shfl_xor_sync(0xffffffffu, d[t], o);
        }
        #pragma unroll
        for (int t = 0; t < 4; t++) {
            float e = d[t] + sop[t] + sma;
            e = fmaxf(e, 0.01f*e);                   // leaky_relu(0.01)
            float p = ok[t] ? __expf(e) : 0.f;       // no max-sub: |e| small
            denom += p;
            accz.x += p*zv[t].x; accz.y += p*zv[t].y;
            accz.z += p*zv[t].z; accz.w += p*zv[t].w;
            acch.x += p*hv[t].x; acch.y += p*hv[t].y;
            acch.z += p*hv[t].z; acch.w += p*hv[t].w;
        }
    }

    // combine halves (disjoint n-sets, same f-layout)
    accz.x += __shfl_xor_sync(0xffffffffu, accz.x, 16);
    accz.y += __shfl_xor_sync(0xffffffffu, accz.y, 16);
    accz.z += __shfl_xor_sync(0xffffffffu, accz.z, 16);
    accz.w += __shfl_xor_sync(0xffffffffu, accz.w, 16);
    acch.x += __shfl_xor_sync(0xffffffffu, acch.x, 16);
    acch.y += __shfl_xor_sync(0xffffffffu, acch.y, 16);
    acch.z += __shfl_xor_sync(0xffffffffu, acch.z, 16);
    acch.w += __shfl_xor_sync(0xffffffffu, acch.w, 16);
    denom  += __shfl_xor_sync(0xffffffffu, denom, 16);

    if (lane < 16) {
        s_pz4[w*16 + l4] = accz;
        s_ph4[w*16 + l4] = acch;
        if (lane == 0) s_pd[w] = denom;
    }
    __syncthreads();

    {
        const int f = tid;
        const float* pz = (const float*)s_pz4;
        const float* ph = (const float*)s_ph4;
        const int slot = sp*NBM + bm;
        g_paccz[slot*F + f] = pz[f] + pz[F+f];
        g_pacch[slot*F + f] = ph[f] + ph[F+f];
        if (tid == 0) g_pd[slot] = s_pd[0] + s_pd[1];
    }
}

// ---------------------------------------------------------------------------
// Epilogue: combine the NSPLIT partials, apply W_edge GEMV, add h, ELU.
// ---------------------------------------------------------------------------
__global__ void __launch_bounds__(64) epilogue_kernel(
    const float* __restrict__ Wedge,
    float*       __restrict__ out)
{
    const int bm = blockIdx.x;
    const int f = threadIdx.x;

    __shared__ float s_accz[F];

    float az = g_paccz[bm*F + f] + g_paccz[(NBM + bm)*F + f];
    float ah = g_pacch[bm*F + f] + g_pacch[(NBM + bm)*F + f];
    float dn = g_pd[bm] + g_pd[NBM + bm];
    s_accz[f] = az;
    __syncthreads();

    float val = ah;
    #pragma unroll
    for (int kk = 0; kk < F; kk++)
        val += s_accz[kk] * Wedge[kk*F + f];
    float hbv = g_h[bm*F + f];
    // row_empty (dn==0): h_prime contribution zeroed -> just h
    float hp = (dn > 0.f) ? (val / dn + hbv) : hbv;
    out[bm*F + f] = (hp > 0.f) ? hp : expm1f(hp);   // ELU
}

extern "C" void kernel_launch(void* const* d_in, const int* in_sizes, int n_in,
                              void* d_out, int out_size)
{
    const float* x    = (const float*)d_in[0];
    const float* y    = (const float*)d_in[1];
    const float* z    = (const float*)d_in[2];
    const int*   adj  = (const int*)  d_in[3];
    const float* Wop  = (const float*)d_in[4];
    const float* Wma  = (const float*)d_in[5];
    const float* We   = (const float*)d_in[6];
    const float* att  = (const float*)d_in[7];
    float* out = (float*)d_out;

    prep_kernel<<<NB*OP + NB*MA + 1, F>>>(x, y, Wop, Wma, We, att);
    dim3 grid(NBM, NSPLIT);
    edge_gat_kernel<<<grid, 64>>>(z, adj);
    epilogue_kernel<<<NBM, F>>>(We, out);
}

// round 15
// speedup vs baseline: 1.3811x; 1.3811x over previous
#include <cuda_runtime.h>

#define NB 8
#define OP 400
#define MA 200
#define F 64
#define NBM (NB*MA)          // 1600
#define ROWS_X (NB*OP)       // 3200
#define ROWS_TOT (ROWS_X + NBM)  // 4800
#define RPB 16               // rows per prep block

// Scratch (allocation-free rule: __device__ globals)
__device__ float g_hop[NB*OP*F];   // h_op = x @ W_op
__device__ float g_sop[NB*OP];     // h_op . a_op
__device__ float g_h  [NB*MA*F];   // h = y @ W_ma
__device__ float g_sma[NB*MA];     // h . a_ma
__device__ float g_vedge[F];       // W_edge @ a_edge

// ---------------------------------------------------------------------------
// Prep kernel (tiled): 300 CTAs x 256 threads. Each CTA stages W (16KB) and
// 16 input rows (4KB) in smem once, then thread (r, cg) computes 4 outputs
// (float4) with 64 smem FMAs. sop = h . a reduced over the 16 same-row lanes
// (4-deep shfl). Block 300 computes v_edge.
// ---------------------------------------------------------------------------
__global__ void __launch_bounds__(256) prep_kernel(
    const float* __restrict__ x, const float* __restrict__ y,
    const float* __restrict__ Wop, const float* __restrict__ Wma,
    const float* __restrict__ Wedge, const float* __restrict__ att)
{
    const int blk = blockIdx.x;
    const int tid = threadIdx.x;

    if (blk == ROWS_TOT / RPB) {           // v_edge block
        if (tid < F) {
            float acc = 0.f;
            #pragma unroll
            for (int f = 0; f < F; f++) acc += Wedge[tid*F + f] * att[2*F + f];
            g_vedge[tid] = acc;
        }
        return;
    }

    const bool isx = blk < (ROWS_X / RPB);
    const float* in  = isx ? x : y;
    const float* W   = isx ? Wop : Wma;
    const float* a   = isx ? att : att + F;
    float* hout      = isx ? g_hop : g_h;
    float* sout      = isx ? g_sop : g_sma;
    const int row0   = isx ? blk * RPB : (blk - ROWS_X / RPB) * RPB;

    __shared__ float sW[F * F];        // 16 KB
    __shared__ float sX[RPB * F];      // 4 KB

    // stage W: 4096 floats = 1024 float4, 256 threads x 4
    {
        const float4* Wsrc = (const float4*)W;
        float4* Wdst = (float4*)sW;
        #pragma unroll
        for (int k = 0; k < 4; k++) Wdst[tid + k*256] = Wsrc[tid + k*256];
    }
    // stage 16 rows: 1024 floats = 256 float4
    {
        const float4* Xsrc = (const float4*)(in + row0 * F);
        ((float4*)sX)[tid] = Xsrc[tid];
    }
    __syncthreads();

    const int r  = tid >> 4;          // 0..15 row within tile
    const int cg = tid & 15;          // 0..15 column group (4 f each)

    float4 acc = make_float4(0.f, 0.f, 0.f, 0.f);
    const float4* sW4 = (const float4*)sW;
    #pragma unroll
    for (int i = 0; i < F; i++) {
        float xv = sX[r*F + i];
        float4 wv = sW4[i*16 + cg];
        acc.x += xv * wv.x; acc.y += xv * wv.y;
        acc.z += xv * wv.z; acc.w += xv * wv.w;
    }

    const int row = row0 + r;
    ((float4*)hout)[row*16 + cg] = acc;

    // sop: dot with a over this thread's 4 f, reduce across 16 same-row lanes
    const float4 a4 = ((const float4*)a)[cg];
    float v = acc.x*a4.x + acc.y*a4.y + acc.z*a4.z + acc.w*a4.w;
    v += __shfl_xor_sync(0xffffffffu, v, 1);
    v += __shfl_xor_sync(0xffffffffu, v, 2);
    v += __shfl_xor_sync(0xffffffffu, v, 4);
    v += __shfl_xor_sync(0xffffffffu, v, 8);
    if (cg == 0) sout[row] = v;
}

// ---------------------------------------------------------------------------
// Main kernel (R8, proven): 64-thread CTA (2 warps) per (b, m) -> all 1600
// CTAs resident in ONE wave. Masked n's compacted into smem. Half-warp per n
// with float4 (each warp instruction covers two n's); 4 units unrolled -> 8
// z-row LDG.128 in flight per warp (MLP=8) to cover DRAM latency.
// Softmax without max-subtraction (|e| small by construction).
// ---------------------------------------------------------------------------
__global__ __launch_bounds__(64) void edge_gat_kernel(
    const float*  __restrict__ z,
    const int*    __restrict__ adj,
    const float*  __restrict__ Wedge,
    float*        __restrict__ out)
{
    const int bid = blockIdx.x;
    const int b = bid / MA;
    const int m = bid % MA;
    const int tid = threadIdx.x;
    const int w = tid >> 5;        // 0 or 1
    const int lane = tid & 31;
    const int l4 = lane & 15;      // float4 slot within half (f = 4*l4..4*l4+3)
    const int hh = lane >> 4;      // half id

    __shared__ int   s_cnt;
    __shared__ int   s_idx[OP];     // compacted masked n
    __shared__ float s_sopc[OP];    // compacted sop values
    __shared__ float4 s_pz4[2*16];
    __shared__ float4 s_ph4[2*16];
    __shared__ float s_pd[2];
    __shared__ float s_accz[F];

    if (tid == 0) s_cnt = 0;
    __syncthreads();

    // ballot-compaction; warp-uniform trip count: 448 = 7 iters for all 64 thr
    for (int i = tid; i < 448; i += 64) {
        int mk = 0;
        float sop = 0.f;
        if (i < OP) {
            mk = adj[(b*OP + i)*MA + m];     // adjT[b,m,i]
            if (mk) sop = g_sop[b*OP + i];
        }
        unsigned ball = __ballot_sync(0xffffffffu, mk != 0);
        int base = 0;
        if (lane == 0 && ball) base = atomicAdd(&s_cnt, __popc(ball));
        base = __shfl_sync(0xffffffffu, base, 0);
        if (mk) {
            int off = base + __popc(ball & ((1u << lane) - 1u));
            s_idx[off]  = i;
            s_sopc[off] = sop;
        }
    }
    const float  sma = g_sma[b*MA + m];
    const float4 ve  = ((const float4*)g_vedge)[l4];
    __syncthreads();
    const int cnt = s_cnt;
    const int U = (cnt + 1) >> 1;    // units of 2 n's

    float4 accz = make_float4(0.f, 0.f, 0.f, 0.f);
    float4 acch = make_float4(0.f, 0.f, 0.f, 0.f);
    float  denom = 0.f;   // per-half replicated; halves disjoint

    const float4* zb4 = (const float4*)z;
    const float4* hb4 = (const float4*)g_hop;

    // warp w handles units u = w + 2k; unrolled x4 -> 8 n (8 z LDG.128) in flight
    #pragma unroll 1
    for (int u0 = w; u0 < U; u0 += 8) {
        bool  ok[4]; float sop[4];
        float4 zv[4], hv[4];
        #pragma unroll
        for (int t = 0; t < 4; t++) {
            int u  = u0 + 2*t;
            int jn = 2*u + hh;
            ok[t] = (u < U) && (jn < cnt);
            int jc = ok[t] ? jn : 0;
            int n  = s_idx[jc];
            sop[t] = s_sopc[jc];
            if (ok[t]) {
                zv[t] = zb4[((b*OP + n)*MA + m)*16 + l4];
                hv[t] = hb4[(b*OP + n)*16 + l4];
            } else {
                zv[t] = make_float4(0.f,0.f,0.f,0.f);
                hv[t] = make_float4(0.f,0.f,0.f,0.f);
            }
        }
        float d[4];
        #pragma unroll
        for (int t = 0; t < 4; t++)
            d[t] = zv[t].x*ve.x + zv[t].y*ve.y + zv[t].z*ve.z + zv[t].w*ve.w;
        // 4-deep butterfly within each 16-lane half; 4 units interleaved
        #pragma unroll
        for (int o = 8; o; o >>= 1) {
            #pragma unroll
            for (int t = 0; t < 4; t++)
                d[t] += __shfl_xor_sync(0xffffffffu, d[t], o);
        }
        #pragma unroll
        for (int t = 0; t < 4; t++) {
            float e = d[t] + sop[t] + sma;
            e = fmaxf(e, 0.01f*e);                   // leaky_relu(0.01)
            float p = ok[t] ? __expf(e) : 0.f;       // no max-sub: |e| small
            denom += p;
            accz.x += p*zv[t].x; accz.y += p*zv[t].y;
            accz.z += p*zv[t].z; accz.w += p*zv[t].w;
            acch.x += p*hv[t].x; acch.y += p*hv[t].y;
            acch.z += p*hv[t].z; acch.w += p*hv[t].w;
        }
    }

    // combine halves (disjoint n-sets, same f-layout)
    accz.x += __shfl_xor_sync(0xffffffffu, accz.x, 16);
    accz.y += __shfl_xor_sync(0xffffffffu, accz.y, 16);
    accz.z += __shfl_xor_sync(0xffffffffu, accz.z, 16);
    accz.w += __shfl_xor_sync(0xffffffffu, accz.w, 16);
    acch.x += __shfl_xor_sync(0xffffffffu, acch.x, 16);
    acch.y += __shfl_xor_sync(0xffffffffu, acch.y, 16);
    acch.z += __shfl_xor_sync(0xffffffffu, acch.z, 16);
    acch.w += __shfl_xor_sync(0xffffffffu, acch.w, 16);
    denom  += __shfl_xor_sync(0xffffffffu, denom, 16);

    if (lane < 16) {
        s_pz4[w*16 + l4] = accz;
        s_ph4[w*16 + l4] = acch;
        if (lane == 0) s_pd[w] = denom;
    }
    __syncthreads();

    {
        const int f = tid;   // 64 threads = 64 features
        const float* pz = (const float*)s_pz4;
        const float* ph = (const float*)s_ph4;
        float az = pz[f] + pz[F+f];
        float ah = ph[f] + ph[F+f];
        float dn = s_pd[0] + s_pd[1];
        s_accz[f] = az;
        __syncthreads();

        float val = ah;
        #pragma unroll
        for (int kk = 0; kk < F; kk++)
            val += s_accz[kk] * Wedge[kk*F + f];
        float hbv = g_h[(b*MA + m)*F + f];
        // row_empty (dn==0): h_prime contribution zeroed -> just h
        float hp = (dn > 0.f) ? (val / dn + hbv) : hbv;
        out[(b*MA + m)*F + f] = (hp > 0.f) ? hp : expm1f(hp);   // ELU
    }
}

extern "C" void kernel_launch(void* const* d_in, const int* in_sizes, int n_in,
                              void* d_out, int out_size)
{
    const float* x    = (const float*)d_in[0];
    const float* y    = (const float*)d_in[1];
    const float* z    = (const float*)d_in[2];
    const int*   adj  = (const int*)  d_in[3];
    const float* Wop  = (const float*)d_in[4];
    const float* Wma  = (const float*)d_in[5];
    const float* We   = (const float*)d_in[6];
    const float* att  = (const float*)d_in[7];
    float* out = (float*)d_out;

    prep_kernel<<<ROWS_TOT / RPB + 1, 256>>>(x, y, Wop, Wma, We, att);
    edge_gat_kernel<<<NBM, 64>>>(z, adj, We, out);
}